// round 2
// baseline (speedup 1.0000x reference)
#include <cuda_runtime.h>
#include <cuda_bf16.h>
#include <cstdint>

typedef __nv_bfloat16 bf16;

#define BB   128
#define TT   256
#define NH   1024
#define NI   1024
#define KK2  2048
#define KC   64
#define APAD 72
#define BPAD 40

#define SMEM_A_ELEMS (2*2*128*APAD)   // [ver][buf][row][col]
#define SMEM_B_ELEMS (2*2*KC*BPAD)    // [ver][buf][k][col]
#define SMEM_BYTES   ((SMEM_A_ELEMS + SMEM_B_ELEMS)*2)

// ---------------- device scratch (static allocation only) ----------------
__device__ float g_s [9][BB*NH];
__device__ bf16  g_sh[9][BB*NH];
__device__ bf16  g_sl[9][BB*NH];
__device__ float g_hbuf[BB*NH];
__device__ bf16  g_hh[BB*NH];
__device__ bf16  g_hl[BB*NH];
__device__ bf16  g_xh[BB*TT*NI];
__device__ bf16  g_xl[BB*TT*NI];
__device__ bf16  g_W0h[KK2*KK2];
__device__ bf16  g_W0l[KK2*KK2];
__device__ bf16  g_Wsh[8*NH*KK2];
__device__ bf16  g_Wsl[8*NH*KK2];
__device__ unsigned g_barrier;

__constant__ int d_src[8] = {0,1,1,1,2,5,3,5};
__constant__ int d_act[8] = {0,1,1,2,3,0,3,1};   // 0 sigmoid, 1 relu, 2 identity, 3 tanh

// ---------------- primitives ----------------
__device__ __forceinline__ void cp16(void* dst, const void* src){
  uint32_t d = (uint32_t)__cvta_generic_to_shared(dst);
  asm volatile("cp.async.cg.shared.global [%0], [%1], 16;\n" :: "r"(d), "l"(src));
}
__device__ __forceinline__ void cp_commit(){ asm volatile("cp.async.commit_group;\n"); }

__device__ __forceinline__ void mma16816(float c[4], const uint32_t a[4], const uint32_t b[2]){
  asm volatile(
    "mma.sync.aligned.m16n8k16.row.col.f32.bf16.bf16.f32 "
    "{%0,%1,%2,%3},{%4,%5,%6,%7},{%8,%9},{%0,%1,%2,%3};\n"
    : "+f"(c[0]), "+f"(c[1]), "+f"(c[2]), "+f"(c[3])
    : "r"(a[0]), "r"(a[1]), "r"(a[2]), "r"(a[3]), "r"(b[0]), "r"(b[1]));
}

__device__ __forceinline__ unsigned ld_acq(unsigned* p){
  unsigned v;
  asm volatile("ld.acquire.gpu.u32 %0, [%1];" : "=r"(v) : "l"(p) : "memory");
  return v;
}
__device__ __forceinline__ void red_rel(unsigned* p){
  asm volatile("red.release.gpu.global.add.u32 [%0], %1;" :: "l"(p), "r"(1u) : "memory");
}
__device__ __forceinline__ void gsync(unsigned &target){
  __syncthreads();
  if (threadIdx.x == 0){
    red_rel(&g_barrier);
    target += gridDim.x;
    while (ld_acq(&g_barrier) < target) __nanosleep(64);
  }
  __syncthreads();
}

// ---------------- fused GEMM tile + gate epilogue ----------------
// CTA tile: M=128 rows, COLS local cols = COLS/2 "c" cols [j, j+COLS/2) paired
// with COLS/2 "h" cols [1024+j, ...). c/h pair lands in the SAME thread.
// COLS=32: 8 warps as 4(M)x2(N), warp = 32 rows x (8c+8h).
// COLS=16: 8 warps as 8(M)x1(N), warp = 16 rows x (8c+8h).
template<int COLS>
__device__ __forceinline__ void gemm_tile(
    const bf16* __restrict__ A1h, const bf16* __restrict__ A1l, long a1s,
    const bf16* __restrict__ A2h, const bf16* __restrict__ A2l,
    const float* __restrict__ resid,
    const bf16* __restrict__ Wh, const bf16* __restrict__ Wl,
    float* __restrict__ outS, bf16* __restrict__ outBh, bf16* __restrict__ outBl,
    int K, int act, int j, bf16* smem, int tid)
{
  constexpr int HALF = COLS/2;
  constexpr int NWN  = (COLS == 32) ? 2 : 1;
  constexpr int MT   = (COLS == 32) ? 2 : 1;    // m16 tiles per warp
  bf16* Asm = smem;
  bf16* Bsm = smem + SMEM_A_ELEMS;
  const int lane = tid & 31, warp = tid >> 5;
  const int wm = warp / NWN, wn = warp % NWN;

  float C[MT][2][4];
  #pragma unroll
  for (int m=0;m<MT;m++)
    #pragma unroll
    for (int n=0;n<2;n++)
      #pragma unroll
      for (int q=0;q<4;q++) C[m][n][q]=0.f;

  auto As_at = [&](int ver,int buf,int r,int c)->bf16*{
    return Asm + (((ver*2+buf)*128 + r)*APAD + c);
  };
  auto Bs_at = [&](int ver,int buf,int k,int c)->bf16*{
    return Bsm + (((ver*2+buf)*KC + k)*BPAD + c);
  };

  auto load_tiles = [&](int buf, int kc){
    const bf16 *ahp, *alp; long astr;
    if (kc < NH){ ahp = A1h + kc;        alp = A1l + kc;        astr = a1s; }
    else        { ahp = A2h + (kc - NH); alp = A2l + (kc - NH); astr = NH;  }
    // A: 2 ver x 128 rows x (KC/8=8) chunks = 2048 chunks
    #pragma unroll
    for (int i=0;i<8;i++){
      int id  = tid + 256*i;
      int ver = id >> 10;
      int rid = id & 1023;
      int row = rid >> 3, ch = rid & 7;
      cp16(As_at(ver, buf, row, ch*8), (ver?alp:ahp) + (size_t)row*astr + ch*8);
    }
    // B: 2 ver x KC rows x (COLS/8) chunks
    constexpr int BCH   = COLS/8;
    constexpr int BITER = (2*KC*BCH)/256;
    #pragma unroll
    for (int i=0;i<BITER;i++){
      int id  = tid + 256*i;
      int ver = id / (KC*BCH);
      int rid = id % (KC*BCH);
      int k = rid / BCH, ch = rid % BCH;
      int c = ch*8;
      int wcol = (c < HALF) ? (j + c) : (NH + j + (c - HALF));
      cp16(Bs_at(ver, buf, k, c), (ver?Wl:Wh) + (size_t)(kc+k)*KK2 + wcol);
    }
    cp_commit();
  };

  load_tiles(0, 0);
  const int nIter = K / KC;
  for (int it = 0; it < nIter; it++){
    const int buf = it & 1;
    if (it + 1 < nIter){
      load_tiles(buf ^ 1, (it+1)*KC);
      asm volatile("cp.async.wait_group 1;\n");
    } else {
      asm volatile("cp.async.wait_group 0;\n");
    }
    __syncthreads();

    #pragma unroll
    for (int k16 = 0; k16 < KC; k16 += 16){
      uint32_t Ah[MT][4], Al[MT][4];
      #pragma unroll
      for (int mt=0; mt<MT; mt++){
        int r = wm*(16*MT) + mt*16 + (lane>>2);
        int c = k16 + 2*(lane&3);
        Ah[mt][0] = *(uint32_t*)As_at(0,buf,r  ,c  );
        Ah[mt][1] = *(uint32_t*)As_at(0,buf,r+8,c  );
        Ah[mt][2] = *(uint32_t*)As_at(0,buf,r  ,c+8);
        Ah[mt][3] = *(uint32_t*)As_at(0,buf,r+8,c+8);
        Al[mt][0] = *(uint32_t*)As_at(1,buf,r  ,c  );
        Al[mt][1] = *(uint32_t*)As_at(1,buf,r+8,c  );
        Al[mt][2] = *(uint32_t*)As_at(1,buf,r  ,c+8);
        Al[mt][3] = *(uint32_t*)As_at(1,buf,r+8,c+8);
      }
      uint32_t Bh[2][2], Bl[2][2];
      #pragma unroll
      for (int nt=0; nt<2; nt++){
        int n = nt*HALF + wn*8 + (lane>>2);
        int k = k16 + 2*(lane&3);
        uint32_t lo, hi;
        lo = *(const uint16_t*)Bs_at(0,buf,k  ,n);
        hi = *(const uint16_t*)Bs_at(0,buf,k+1,n);
        Bh[nt][0] = lo | (hi<<16);
        lo = *(const uint16_t*)Bs_at(0,buf,k+8,n);
        hi = *(const uint16_t*)Bs_at(0,buf,k+9,n);
        Bh[nt][1] = lo | (hi<<16);
        lo = *(const uint16_t*)Bs_at(1,buf,k  ,n);
        hi = *(const uint16_t*)Bs_at(1,buf,k+1,n);
        Bl[nt][0] = lo | (hi<<16);
        lo = *(const uint16_t*)Bs_at(1,buf,k+8,n);
        hi = *(const uint16_t*)Bs_at(1,buf,k+9,n);
        Bl[nt][1] = lo | (hi<<16);
      }
      #pragma unroll
      for (int mt=0; mt<MT; mt++)
        #pragma unroll
        for (int nt=0; nt<2; nt++){
          mma16816(C[mt][nt], Ah[mt], Bh[nt]);   // Ah*Wh
          mma16816(C[mt][nt], Al[mt], Bh[nt]);   // Al*Wh
          mma16816(C[mt][nt], Ah[mt], Bl[nt]);   // Ah*Wl
        }
    }
    __syncthreads();
  }

  // epilogue: s_next = s_prev + sigmoid(ch_c) * (act(ch_h) - s_prev)
  #pragma unroll
  for (int mt=0; mt<MT; mt++){
    #pragma unroll
    for (int q=0; q<4; q++){
      int r  = wm*(16*MT) + mt*16 + (lane>>2) + ((q>=2)?8:0);
      int cl = wn*8 + 2*(lane&3) + (q&1);
      float cv = C[mt][0][q];
      float hv = C[mt][1][q];
      float gate = 1.f/(1.f + __expf(-cv));
      float h;
      switch (act){
        case 0:  h = 1.f/(1.f + __expf(-hv)); break;
        case 1:  h = fmaxf(hv, 0.f);          break;
        case 2:  h = hv;                      break;
        default: h = tanhf(hv);               break;
      }
      int idx = r*NH + j + cl;
      float sp = __ldcg(resid + idx);          // L2-coherent (L1 not flushed at grid barriers)
      float v  = fmaf(gate, h - sp, sp);
      outS[idx] = v;
      bf16 vh = __float2bfloat16(v);
      outBh[idx] = vh;
      outBl[idx] = __float2bfloat16(v - __bfloat162float(vh));
    }
  }
}

// ---------------- persistent scan kernel ----------------
__global__ void __launch_bounds__(256,1) rnn_persistent(float* __restrict__ out){
  extern __shared__ __align__(16) bf16 smem[];
  const int tid = threadIdx.x;
  unsigned target = 0;

  for (int t = 0; t < TT; t++){
    // P0: s0 = h + sig(c)*(tanh(h') - h), A=[x_t | h], K=2048, 128 tiles of 8 pairs
    for (int tile = blockIdx.x; tile < 128; tile += gridDim.x)
      gemm_tile<16>(g_xh + (size_t)t*NI, g_xl + (size_t)t*NI, (long)TT*NI,
                    g_hh, g_hl, g_hbuf, g_W0h, g_W0l,
                    g_s[0], g_sh[0], g_sl[0], KK2, 3, tile*8, smem, tid);
    gsync(target);

    // P1: gene0 (sigmoid) s0 -> s1, 128 tiles of 8 pairs
    for (int tile = blockIdx.x; tile < 128; tile += gridDim.x)
      gemm_tile<16>(g_sh[0], g_sl[0], NH, g_sh[0], g_sl[0], g_s[0],
                    g_Wsh, g_Wsl, g_s[1], g_sh[1], g_sl[1],
                    NH, 0, tile*8, smem, tid);
    gsync(target);

    // P2: genes 1,2,3 from s1 (relu, relu, identity), 3 x 64 tiles of 16 pairs
    for (int it = blockIdx.x; it < 192; it += gridDim.x){
      int gi = 1 + (it >> 6), tile = it & 63;
      int s = d_src[gi];
      gemm_tile<32>(g_sh[s], g_sl[s], NH, g_sh[s], g_sl[s], g_s[s],
                    g_Wsh + (size_t)gi*NH*KK2, g_Wsl + (size_t)gi*NH*KK2,
                    g_s[gi+1], g_sh[gi+1], g_sl[gi+1],
                    NH, d_act[gi], tile*16, smem, tid);
    }
    gsync(target);

    // P3: gene4 (tanh) s2->s5 ; gene6 (tanh) s3->s7
    for (int it = blockIdx.x; it < 128; it += gridDim.x){
      int gi = (it >= 64) ? 6 : 4, tile = it & 63;
      int s = d_src[gi];
      gemm_tile<32>(g_sh[s], g_sl[s], NH, g_sh[s], g_sl[s], g_s[s],
                    g_Wsh + (size_t)gi*NH*KK2, g_Wsl + (size_t)gi*NH*KK2,
                    g_s[gi+1], g_sh[gi+1], g_sl[gi+1],
                    NH, d_act[gi], tile*16, smem, tid);
    }
    gsync(target);

    // P4: gene5 (sigmoid) s5->s6 ; gene7 (relu) s5->s8
    for (int it = blockIdx.x; it < 128; it += gridDim.x){
      int gi = (it >= 64) ? 7 : 5, tile = it & 63;
      int s = d_src[gi];
      gemm_tile<32>(g_sh[s], g_sl[s], NH, g_sh[s], g_sl[s], g_s[s],
                    g_Wsh + (size_t)gi*NH*KK2, g_Wsl + (size_t)gi*NH*KK2,
                    g_s[gi+1], g_sh[gi+1], g_sl[gi+1],
                    NH, d_act[gi], tile*16, smem, tid);
    }
    gsync(target);

    // P5: h = mean(s1..s8); emit hiddens[b, t, :]; bf16 hi/lo shadows
    for (int i = blockIdx.x*256 + tid; i < BB*NH; i += gridDim.x*256){
      float s = 0.f;
      #pragma unroll
      for (int k=1;k<9;k++) s += __ldcg(&g_s[k][i]);
      s *= 0.125f;
      g_hbuf[i] = s;
      bf16 bh = __float2bfloat16(s);
      g_hh[i] = bh;
      g_hl[i] = __float2bfloat16(s - __bfloat162float(bh));
      int b = i >> 10, jj = i & 1023;
      out[((size_t)b*TT + t)*NH + jj] = s;
      if (t == TT-1) out[(size_t)BB*TT*NH + i] = s;
    }
    gsync(target);
  }
}

// ---------------- helpers ----------------
__global__ void split_kernel(const float* __restrict__ src, bf16* __restrict__ hi,
                             bf16* __restrict__ lo, float* __restrict__ fcopy, int n){
  int i = blockIdx.x*blockDim.x + threadIdx.x;
  int stride = gridDim.x*blockDim.x;
  for (; i < n; i += stride){
    float v = src[i];
    bf16 h = __float2bfloat16(v);
    hi[i] = h;
    lo[i] = __float2bfloat16(v - __bfloat162float(h));
    if (fcopy) fcopy[i] = v;
  }
}

__global__ void reset_kernel(){ g_barrier = 0; }

// ---------------- host launch ----------------
extern "C" void kernel_launch(void* const* d_in, const int* in_sizes, int n_in,
                              void* d_out, int out_size){
  const float *x=nullptr, *h0=nullptr, *W0=nullptr, *Ws=nullptr;
  for (int i=0;i<n_in;i++){
    long n = in_sizes[i];
    if      (n == (long)BB*TT*NI) x  = (const float*)d_in[i];
    else if (n == (long)BB*NH)    h0 = (const float*)d_in[i];
    else if (n == (long)KK2*KK2)  W0 = (const float*)d_in[i];
    else if (n == (long)8*NH*KK2) Ws = (const float*)d_in[i];
  }
  if (!x || !h0 || !W0 || !Ws) return;
  float* out = (float*)d_out;

  void* p;
  cudaGetSymbolAddress(&p, g_hbuf); float* h_p  = (float*)p;
  cudaGetSymbolAddress(&p, g_hh);   bf16*  hh_p = (bf16*)p;
  cudaGetSymbolAddress(&p, g_hl);   bf16*  hl_p = (bf16*)p;
  cudaGetSymbolAddress(&p, g_xh);   bf16*  xh_p = (bf16*)p;
  cudaGetSymbolAddress(&p, g_xl);   bf16*  xl_p = (bf16*)p;
  cudaGetSymbolAddress(&p, g_W0h);  bf16*  w0h_p= (bf16*)p;
  cudaGetSymbolAddress(&p, g_W0l);  bf16*  w0l_p= (bf16*)p;
  cudaGetSymbolAddress(&p, g_Wsh);  bf16*  wsh_p= (bf16*)p;
  cudaGetSymbolAddress(&p, g_Wsl);  bf16*  wsl_p= (bf16*)p;

  cudaFuncSetAttribute(rnn_persistent, cudaFuncAttributeMaxDynamicSharedMemorySize, SMEM_BYTES);

  int dev = 0, nsm = 0, maxblk = 0;
  cudaGetDevice(&dev);
  cudaDeviceGetAttribute(&nsm, cudaDevAttrMultiProcessorCount, dev);
  cudaOccupancyMaxActiveBlocksPerMultiprocessor(&maxblk, rnn_persistent, 256, SMEM_BYTES);
  if (maxblk < 1) maxblk = 1;
  int grid = nsm * maxblk;

  // prologue: bf16 hi/lo splits of weights, inputs, initial hidden
  split_kernel<<<2048,256>>>(W0, w0h_p, w0l_p, nullptr, KK2*KK2);
  split_kernel<<<4096,256>>>(Ws, wsh_p, wsl_p, nullptr, 8*NH*KK2);
  split_kernel<<<8192,256>>>(x,  xh_p,  xl_p,  nullptr, BB*TT*NI);
  split_kernel<<<512,256>>>(h0, hh_p, hl_p, h_p, BB*NH);
  reset_kernel<<<1,1>>>();

  rnn_persistent<<<grid, 256, SMEM_BYTES>>>(out);
  (void)out_size;
}

// round 3
// speedup vs baseline: 1.6287x; 1.6287x over previous
#include <cuda_runtime.h>
#include <cuda_bf16.h>
#include <cstdint>

typedef __nv_bfloat16 bf16;

#define BB   128
#define TT   256
#define NH   1024
#define NI   1024
#define NT   512              // threads per CTA
#define KB   32               // inner k chunk
#define KC   128              // k-slice per tile
#define PAD  40               // padded row stride (elems) for A/B smem

#define SA_ELEMS (2*2*128*PAD)     // [ver][buf][row][PAD]
#define SB_ELEMS (2*2*128*PAD)     // [ver][buf][n][PAD]
#define SMEM_BYTES ((SA_ELEMS + SB_ELEMS)*2)

// ---------------- device scratch ----------------
__device__ float g_s [9][BB*NH];
__device__ bf16  g_sh[6][BB*NH];     // bf16 shadows only for s0,s1,s2,s3,(4 unused),s5
__device__ bf16  g_sl[6][BB*NH];
__device__ float g_hbuf[BB*NH];
__device__ bf16  g_hh[BB*NH];
__device__ bf16  g_hl[BB*NH];
__device__ bf16  g_xh[BB*TT*NI];
__device__ bf16  g_xl[BB*TT*NI];
__device__ bf16  g_W0th[2048*2048];  // transposed: [n][k]
__device__ bf16  g_W0tl[2048*2048];
__device__ bf16  g_Wsth[8][2048*1024];
__device__ bf16  g_Wstl[8][2048*1024];
__device__ float g_part[16*3][BB*2048];   // [slice*3+slot][row][gcol]
__device__ unsigned g_barrier;

// ---------------- primitives ----------------
__device__ __forceinline__ void cp16(void* dst, const void* src){
  uint32_t d = (uint32_t)__cvta_generic_to_shared(dst);
  asm volatile("cp.async.cg.shared.global [%0], [%1], 16;\n" :: "r"(d), "l"(src));
}
__device__ __forceinline__ void cp_commit(){ asm volatile("cp.async.commit_group;\n"); }

__device__ __forceinline__ void mma16816(float c[4], const uint32_t a[4], const uint32_t b[2]){
  asm volatile(
    "mma.sync.aligned.m16n8k16.row.col.f32.bf16.bf16.f32 "
    "{%0,%1,%2,%3},{%4,%5,%6,%7},{%8,%9},{%0,%1,%2,%3};\n"
    : "+f"(c[0]), "+f"(c[1]), "+f"(c[2]), "+f"(c[3])
    : "r"(a[0]), "r"(a[1]), "r"(a[2]), "r"(a[3]), "r"(b[0]), "r"(b[1]));
}

__device__ __forceinline__ unsigned ld_acq(unsigned* p){
  unsigned v;
  asm volatile("ld.acquire.gpu.u32 %0, [%1];" : "=r"(v) : "l"(p) : "memory");
  return v;
}
__device__ __forceinline__ void red_rel(unsigned* p){
  asm volatile("red.release.gpu.global.add.u32 [%0], %1;" :: "l"(p), "r"(1u) : "memory");
}
__device__ __forceinline__ void gsync(unsigned &target){
  __syncthreads();
  if (threadIdx.x == 0){
    red_rel(&g_barrier);
    target += gridDim.x;
    int spins = 0;
    while (ld_acq(&g_barrier) < target){
      if (++spins > 64) __nanosleep(64);
    }
  }
  __syncthreads();
}

__device__ __forceinline__ float act_fn(int act, float v){
  switch (act){
    case 0:  return 1.f/(1.f + __expf(-v));
    case 1:  return fmaxf(v, 0.f);
    case 2:  return v;
    default: return tanhf(v);
  }
}

// ---------------- split-K GEMM tile ----------------
// M=128 (batch), N=128 local (64 c-cols at [j,j+64) + 64 h-cols at [1024+j,...)),
// K-slice = KC = 128. 16 warps in 4(M)x4(N); warp tile 32m x 32n (16c + 16h paired
// per thread). Partials (fp32) stored to g_part.
// ah/al/wh/wl are pre-offset to the k-slice start (kc0).
__device__ __forceinline__ void gemm_tile(
    const bf16* __restrict__ ah, const bf16* __restrict__ al, long astr,
    const bf16* __restrict__ wh, const bf16* __restrict__ wl, int Kw,
    float* __restrict__ part, int j, bf16* smem, int tid)
{
  bf16* Asm = smem;
  bf16* Bsm = smem + SA_ELEMS;
  const int lane = tid & 31, warp = tid >> 5;
  const int wm = warp >> 2, wn = warp & 3;

  float C[2][4][4];
  #pragma unroll
  for (int m=0;m<2;m++)
    #pragma unroll
    for (int n=0;n<4;n++)
      #pragma unroll
      for (int q=0;q<4;q++) C[m][n][q]=0.f;

  auto As_at = [&](int ver,int buf,int r,int c)->bf16*{
    return Asm + (((ver*2+buf)*128 + r)*PAD + c);
  };
  auto Bs_at = [&](int ver,int buf,int n,int c)->bf16*{
    return Bsm + (((ver*2+buf)*128 + n)*PAD + c);
  };

  auto load_tiles = [&](int buf, int cc){
    const int koff = cc*KB;
    #pragma unroll
    for (int i=0;i<2;i++){               // A: 1024 16B-chunks
      int id  = tid + NT*i;
      int ver = id >> 9;
      int rid = id & 511;
      int row = rid >> 2, ch = rid & 3;
      cp16(As_at(ver, buf, row, ch*8), (ver?al:ah) + (size_t)row*astr + koff + ch*8);
    }
    #pragma unroll
    for (int i=0;i<2;i++){               // B: 1024 16B-chunks
      int id  = tid + NT*i;
      int ver = id >> 9;
      int rid = id & 511;
      int n = rid >> 2, ch = rid & 3;
      int wblk = n >> 5, idx = n & 31;
      int gcol = (idx < 16) ? (j + wblk*16 + idx) : (NH + j + wblk*16 + idx - 16);
      cp16(Bs_at(ver, buf, n, ch*8), (ver?wl:wh) + (size_t)gcol*Kw + koff + ch*8);
    }
    cp_commit();
  };

  load_tiles(0, 0);
  #pragma unroll
  for (int cc = 0; cc < KC/KB; cc++){
    const int buf = cc & 1;
    if (cc + 1 < KC/KB){
      load_tiles(buf ^ 1, cc+1);
      asm volatile("cp.async.wait_group 1;\n");
    } else {
      asm volatile("cp.async.wait_group 0;\n");
    }
    __syncthreads();

    #pragma unroll
    for (int k16 = 0; k16 < KB; k16 += 16){
      uint32_t Ah[2][4], Al[2][4];
      #pragma unroll
      for (int mt=0; mt<2; mt++){
        int r = wm*32 + mt*16 + (lane>>2);
        int c = k16 + 2*(lane&3);
        Ah[mt][0] = *(uint32_t*)As_at(0,buf,r  ,c  );
        Ah[mt][1] = *(uint32_t*)As_at(0,buf,r+8,c  );
        Ah[mt][2] = *(uint32_t*)As_at(0,buf,r  ,c+8);
        Ah[mt][3] = *(uint32_t*)As_at(0,buf,r+8,c+8);
        Al[mt][0] = *(uint32_t*)As_at(1,buf,r  ,c  );
        Al[mt][1] = *(uint32_t*)As_at(1,buf,r+8,c  );
        Al[mt][2] = *(uint32_t*)As_at(1,buf,r  ,c+8);
        Al[mt][3] = *(uint32_t*)As_at(1,buf,r+8,c+8);
      }
      uint32_t Bh[4][2], Bl[4][2];
      #pragma unroll
      for (int nt=0; nt<4; nt++){
        int n = wn*32 + nt*8 + (lane>>2);
        int k = k16 + 2*(lane&3);
        Bh[nt][0] = *(uint32_t*)Bs_at(0,buf,n,k);
        Bh[nt][1] = *(uint32_t*)Bs_at(0,buf,n,k+8);
        Bl[nt][0] = *(uint32_t*)Bs_at(1,buf,n,k);
        Bl[nt][1] = *(uint32_t*)Bs_at(1,buf,n,k+8);
      }
      #pragma unroll
      for (int mt=0; mt<2; mt++)
        #pragma unroll
        for (int nt=0; nt<4; nt++){
          mma16816(C[mt][nt], Ah[mt], Bh[nt]);
          mma16816(C[mt][nt], Al[mt], Bh[nt]);
          mma16816(C[mt][nt], Ah[mt], Bl[nt]);
        }
    }
    __syncthreads();
  }

  // store fp32 partials (vectorized float2)
  #pragma unroll
  for (int mt=0; mt<2; mt++){
    #pragma unroll
    for (int nt=0; nt<4; nt++){
      int r0 = wm*32 + mt*16 + (lane>>2);
      int gcol = (nt<2) ? (j + wn*16 + nt*8 + 2*(lane&3))
                        : (NH + j + wn*16 + (nt-2)*8 + 2*(lane&3));
      *(float2*)(part + (size_t)r0*2048 + gcol)     = make_float2(C[mt][nt][0], C[mt][nt][1]);
      *(float2*)(part + (size_t)(r0+8)*2048 + gcol) = make_float2(C[mt][nt][2], C[mt][nt][3]);
    }
  }
}

__device__ __forceinline__ float* part_ptr(int slice, int slot){
  return g_part[slice*3 + slot];
}

// ---------------- persistent scan kernel ----------------
__global__ void __launch_bounds__(NT,1) rnn_persistent(float* __restrict__ out){
  extern __shared__ __align__(16) bf16 smem[];
  const int tid = threadIdx.x;
  unsigned target = 0;

  for (int t = 0; t < TT; t++){
    // ---- G0: ch = [x_t | h] @ W0, K=2048, 16 slices x 16 ntiles ----
    for (int it = blockIdx.x; it < 256; it += gridDim.x){
      int ntile = it >> 4, slice = it & 15;
      int kc0 = slice*KC;
      const bf16 *ah, *al; long astr;
      if (kc0 < 1024){ ah = g_xh + (size_t)t*NI + kc0; al = g_xl + (size_t)t*NI + kc0; astr = (long)TT*NI; }
      else           { ah = g_hh + (kc0-1024);         al = g_hl + (kc0-1024);         astr = NH; }
      gemm_tile(ah, al, astr, g_W0th + kc0, g_W0tl + kc0, 2048,
                part_ptr(slice,0), ntile*64, smem, tid);
    }
    gsync(target);
    // ---- E0: s0 = h + sig(c)*(tanh(hh) - h) ----
    for (int id = blockIdx.x*NT + tid; id < BB*NH; id += gridDim.x*NT){
      int row = id >> 10, col = id & 1023;
      float c = 0.f, hv = 0.f;
      #pragma unroll
      for (int s=0;s<16;s++){
        const float* p = part_ptr(s,0) + (size_t)row*2048;
        c  += __ldcg(p + col);
        hv += __ldcg(p + 1024 + col);
      }
      float sp = __ldcg(g_hbuf + id);
      float v = fmaf(1.f/(1.f+__expf(-c)), tanhf(hv) - sp, sp);
      g_s[0][id] = v;
      bf16 vh = __float2bfloat16(v);
      g_sh[0][id] = vh;
      g_sl[0][id] = __float2bfloat16(v - __bfloat162float(vh));
    }
    gsync(target);

    // ---- G1: gene0 (s0 @ W[0]), 8 slices x 16 ----
    for (int it = blockIdx.x; it < 128; it += gridDim.x){
      int ntile = it >> 3, slice = it & 7;
      int kc0 = slice*KC;
      gemm_tile(g_sh[0] + kc0, g_sl[0] + kc0, NH,
                g_Wsth[0] + kc0, g_Wstl[0] + kc0, 1024,
                part_ptr(slice,0), ntile*64, smem, tid);
    }
    gsync(target);
    // ---- E1: s1 (act sigmoid, resid s0) ----
    for (int id = blockIdx.x*NT + tid; id < BB*NH; id += gridDim.x*NT){
      int row = id >> 10, col = id & 1023;
      float c = 0.f, hv = 0.f;
      #pragma unroll
      for (int s=0;s<8;s++){
        const float* p = part_ptr(s,0) + (size_t)row*2048;
        c  += __ldcg(p + col);
        hv += __ldcg(p + 1024 + col);
      }
      float sp = __ldcg(&g_s[0][id]);
      float v = fmaf(1.f/(1.f+__expf(-c)), act_fn(0,hv) - sp, sp);
      g_s[1][id] = v;
      bf16 vh = __float2bfloat16(v);
      g_sh[1][id] = vh;
      g_sl[1][id] = __float2bfloat16(v - __bfloat162float(vh));
    }
    gsync(target);

    // ---- G2: genes 1,2,3 from s1; 3 slots x 16 ntiles x 8 slices ----
    for (int it = blockIdx.x; it < 384; it += gridDim.x){
      int slot = it >> 7, rem = it & 127;
      int ntile = rem >> 3, slice = rem & 7;
      int gi = 1 + slot;
      int kc0 = slice*KC;
      gemm_tile(g_sh[1] + kc0, g_sl[1] + kc0, NH,
                g_Wsth[gi] + kc0, g_Wstl[gi] + kc0, 1024,
                part_ptr(slice,slot), ntile*64, smem, tid);
    }
    gsync(target);
    // ---- E2: s2 (relu), s3 (relu), s4 (identity); resid s1 ----
    for (int id = blockIdx.x*NT + tid; id < 3*BB*NH; id += gridDim.x*NT){
      int slot = id >> 17, rid = id & (BB*NH-1);
      int row = rid >> 10, col = rid & 1023;
      float c = 0.f, hv = 0.f;
      #pragma unroll
      for (int s=0;s<8;s++){
        const float* p = part_ptr(s,slot) + (size_t)row*2048;
        c  += __ldcg(p + col);
        hv += __ldcg(p + 1024 + col);
      }
      int act = (slot==2) ? 2 : 1;
      float sp = __ldcg(&g_s[1][rid]);
      float v = fmaf(1.f/(1.f+__expf(-c)), act_fn(act,hv) - sp, sp);
      int dst = slot + 2;
      g_s[dst][rid] = v;
      if (dst < 4){
        bf16 vh = __float2bfloat16(v);
        g_sh[dst][rid] = vh;
        g_sl[dst][rid] = __float2bfloat16(v - __bfloat162float(vh));
      }
    }
    gsync(target);

    // ---- G3: gene4 (s2) slot0, gene6 (s3) slot1 ----
    for (int it = blockIdx.x; it < 256; it += gridDim.x){
      int slot = it >> 7, rem = it & 127;
      int ntile = rem >> 3, slice = rem & 7;
      int gi = 4 + slot*2;         // 4, 6
      int src = 2 + slot;          // s2, s3
      int kc0 = slice*KC;
      gemm_tile(g_sh[src] + kc0, g_sl[src] + kc0, NH,
                g_Wsth[gi] + kc0, g_Wstl[gi] + kc0, 1024,
                part_ptr(slice,slot), ntile*64, smem, tid);
    }
    gsync(target);
    // ---- E3: s5 (tanh, resid s2), s7 (tanh, resid s3) ----
    for (int id = blockIdx.x*NT + tid; id < 2*BB*NH; id += gridDim.x*NT){
      int slot = id >> 17, rid = id & (BB*NH-1);
      int row = rid >> 10, col = rid & 1023;
      float c = 0.f, hv = 0.f;
      #pragma unroll
      for (int s=0;s<8;s++){
        const float* p = part_ptr(s,slot) + (size_t)row*2048;
        c  += __ldcg(p + col);
        hv += __ldcg(p + 1024 + col);
      }
      float sp = __ldcg(&g_s[2+slot][rid]);
      float v = fmaf(1.f/(1.f+__expf(-c)), tanhf(hv) - sp, sp);
      int dst = (slot==0) ? 5 : 7;
      g_s[dst][rid] = v;
      if (dst == 5){
        bf16 vh = __float2bfloat16(v);
        g_sh[5][rid] = vh;
        g_sl[5][rid] = __float2bfloat16(v - __bfloat162float(vh));
      }
    }
    gsync(target);

    // ---- G4: gene5 slot0, gene7 slot1, both from s5 ----
    for (int it = blockIdx.x; it < 256; it += gridDim.x){
      int slot = it >> 7, rem = it & 127;
      int ntile = rem >> 3, slice = rem & 7;
      int gi = 5 + slot*2;         // 5, 7
      int kc0 = slice*KC;
      gemm_tile(g_sh[5] + kc0, g_sl[5] + kc0, NH,
                g_Wsth[gi] + kc0, g_Wstl[gi] + kc0, 1024,
                part_ptr(slice,slot), ntile*64, smem, tid);
    }
    gsync(target);
    // ---- E4 + finalize: s6 (sig), s8 (relu), resid s5; h = mean(s1..s8) ----
    for (int id = blockIdx.x*NT + tid; id < BB*NH; id += gridDim.x*NT){
      int row = id >> 10, col = id & 1023;
      float c6=0.f, h6=0.f, c8=0.f, h8=0.f;
      #pragma unroll
      for (int s=0;s<8;s++){
        const float* p0 = part_ptr(s,0) + (size_t)row*2048;
        const float* p1 = part_ptr(s,1) + (size_t)row*2048;
        c6 += __ldcg(p0 + col);  h6 += __ldcg(p0 + 1024 + col);
        c8 += __ldcg(p1 + col);  h8 += __ldcg(p1 + 1024 + col);
      }
      float s5 = __ldcg(&g_s[5][id]);
      float s6 = fmaf(1.f/(1.f+__expf(-c6)), (1.f/(1.f+__expf(-h6))) - s5, s5);
      float s8 = fmaf(1.f/(1.f+__expf(-c8)), fmaxf(h8,0.f) - s5, s5);
      float m = __ldcg(&g_s[1][id]) + __ldcg(&g_s[2][id]) + __ldcg(&g_s[3][id])
              + __ldcg(&g_s[4][id]) + s5 + s6 + __ldcg(&g_s[7][id]) + s8;
      m *= 0.125f;
      g_hbuf[id] = m;
      bf16 mh = __float2bfloat16(m);
      g_hh[id] = mh;
      g_hl[id] = __float2bfloat16(m - __bfloat162float(mh));
      out[((size_t)row*TT + t)*NH + col] = m;
      if (t == TT-1) out[(size_t)BB*TT*NH + id] = m;
    }
    gsync(target);
  }
}

// ---------------- prologue helpers ----------------
__global__ void split_kernel(const float* __restrict__ src, bf16* __restrict__ hi,
                             bf16* __restrict__ lo, float* __restrict__ fcopy, int n){
  int i = blockIdx.x*blockDim.x + threadIdx.x;
  int stride = gridDim.x*blockDim.x;
  for (; i < n; i += stride){
    float v = src[i];
    bf16 h = __float2bfloat16(v);
    hi[i] = h;
    lo[i] = __float2bfloat16(v - __bfloat162float(h));
    if (fcopy) fcopy[i] = v;
  }
}

// transpose + hi/lo split: in [K][N] fp32 -> out [N][K] bf16 x2. One z-slice per gene.
__global__ void tsplit_kernel(const float* __restrict__ in, bf16* __restrict__ outh,
                              bf16* __restrict__ outl, int K, int N){
  __shared__ float tile[32][33];
  const float* src = in + (size_t)blockIdx.z*K*N;
  bf16* oh = outh + (size_t)blockIdx.z*N*K;
  bf16* ol = outl + (size_t)blockIdx.z*N*K;
  int tx = threadIdx.x, ty = threadIdx.y;
  int n0 = blockIdx.x*32, k0 = blockIdx.y*32;
  #pragma unroll
  for (int r=0;r<4;r++)
    tile[ty + r*8][tx] = src[(size_t)(k0 + ty + r*8)*N + n0 + tx];
  __syncthreads();
  #pragma unroll
  for (int r=0;r<4;r++){
    float v = tile[tx][ty + r*8];
    size_t o = (size_t)(n0 + ty + r*8)*K + k0 + tx;
    bf16 h = __float2bfloat16(v);
    oh[o] = h;
    ol[o] = __float2bfloat16(v - __bfloat162float(h));
  }
}

__global__ void reset_kernel(){ g_barrier = 0; }

// ---------------- host launch ----------------
extern "C" void kernel_launch(void* const* d_in, const int* in_sizes, int n_in,
                              void* d_out, int out_size){
  const float *x=nullptr, *h0=nullptr, *W0=nullptr, *Ws=nullptr;
  for (int i=0;i<n_in;i++){
    long n = in_sizes[i];
    if      (n == (long)BB*TT*NI)   x  = (const float*)d_in[i];
    else if (n == (long)BB*NH)      h0 = (const float*)d_in[i];
    else if (n == (long)2048*2048)  W0 = (const float*)d_in[i];
    else if (n == (long)8*NH*2048)  Ws = (const float*)d_in[i];
  }
  if (!x || !h0 || !W0 || !Ws) return;
  float* out = (float*)d_out;

  void* p;
  cudaGetSymbolAddress(&p, g_hbuf); float* h_p  = (float*)p;
  cudaGetSymbolAddress(&p, g_hh);   bf16*  hh_p = (bf16*)p;
  cudaGetSymbolAddress(&p, g_hl);   bf16*  hl_p = (bf16*)p;
  cudaGetSymbolAddress(&p, g_xh);   bf16*  xh_p = (bf16*)p;
  cudaGetSymbolAddress(&p, g_xl);   bf16*  xl_p = (bf16*)p;
  cudaGetSymbolAddress(&p, g_W0th); bf16*  w0h_p= (bf16*)p;
  cudaGetSymbolAddress(&p, g_W0tl); bf16*  w0l_p= (bf16*)p;
  cudaGetSymbolAddress(&p, g_Wsth); bf16*  wsh_p= (bf16*)p;
  cudaGetSymbolAddress(&p, g_Wstl); bf16*  wsl_p= (bf16*)p;

  cudaFuncSetAttribute(rnn_persistent, cudaFuncAttributeMaxDynamicSharedMemorySize, SMEM_BYTES);

  int dev = 0, nsm = 0, maxblk = 0;
  cudaGetDevice(&dev);
  cudaDeviceGetAttribute(&nsm, cudaDevAttrMultiProcessorCount, dev);
  cudaOccupancyMaxActiveBlocksPerMultiprocessor(&maxblk, rnn_persistent, NT, SMEM_BYTES);
  if (maxblk < 1) maxblk = 1;
  int grid = nsm * maxblk;

  // prologue: transpose+split weights, split inputs and initial hidden
  tsplit_kernel<<<dim3(64,64,1), dim3(32,8)>>>(W0, w0h_p, w0l_p, 2048, 2048);
  tsplit_kernel<<<dim3(64,32,8), dim3(32,8)>>>(Ws, wsh_p, wsl_p, 1024, 2048);
  split_kernel<<<8192,256>>>(x, xh_p, xl_p, nullptr, BB*TT*NI);
  split_kernel<<<512,256>>>(h0, hh_p, hl_p, h_p, BB*NH);
  reset_kernel<<<1,1>>>();

  rnn_persistent<<<grid, NT, SMEM_BYTES>>>(out);
  (void)out_size;
}

// round 4
// speedup vs baseline: 1.7777x; 1.0915x over previous
#include <cuda_runtime.h>
#include <cuda_bf16.h>
#include <cstdint>

typedef __nv_bfloat16 bf16;

#define BB   128
#define TT   256
#define NH   1024
#define NI   1024
#define NT   512              // threads per CTA (16 warps)
#define KB   32               // inner k chunk
#define KC   256              // k-slice per tile
#define APAD 40
#define BPAD 40

#define SA_ELEMS (2*2*128*APAD)    // [ver][buf][row][APAD]
#define SB_ELEMS (2*64*BPAD)       // [buf][n][BPAD]
#define SMEM_BYTES ((SA_ELEMS + SB_ELEMS)*2)

// ---------------- device scratch ----------------
__device__ float g_s [9][BB*NH];
__device__ bf16  g_sh[6][BB*NH];     // bf16 shadows for s0,s1,s2,s3,(unused),s5
__device__ bf16  g_sl[6][BB*NH];
__device__ float g_hbuf[BB*NH];
__device__ bf16  g_hh[BB*NH];
__device__ bf16  g_hl[BB*NH];
__device__ bf16  g_xh[BB*TT*NI];
__device__ bf16  g_xl[BB*TT*NI];
__device__ bf16  g_W0th[2048*2048];      // transposed hi: [n][k]
__device__ bf16  g_Wsth[8][2048*1024];   // transposed hi per gene: [n][k]
__device__ float g_part[8*3][BB*2048];   // [slice*3+slot][row][gcol]
__device__ unsigned g_arrive, g_epoch;

// ---------------- primitives ----------------
__device__ __forceinline__ void cp16(void* dst, const void* src){
  uint32_t d = (uint32_t)__cvta_generic_to_shared(dst);
  asm volatile("cp.async.cg.shared.global [%0], [%1], 16;\n" :: "r"(d), "l"(src));
}
__device__ __forceinline__ void cp_commit(){ asm volatile("cp.async.commit_group;\n"); }

__device__ __forceinline__ void mma16816(float c[4], const uint32_t a[4], const uint32_t b[2]){
  asm volatile(
    "mma.sync.aligned.m16n8k16.row.col.f32.bf16.bf16.f32 "
    "{%0,%1,%2,%3},{%4,%5,%6,%7},{%8,%9},{%0,%1,%2,%3};\n"
    : "+f"(c[0]), "+f"(c[1]), "+f"(c[2]), "+f"(c[3])
    : "r"(a[0]), "r"(a[1]), "r"(a[2]), "r"(a[3]), "r"(b[0]), "r"(b[1]));
}

__device__ __forceinline__ void gsync(unsigned &target){
  __syncthreads();
  if (threadIdx.x == 0){
    target += gridDim.x;
    unsigned old;
    asm volatile("atom.add.release.gpu.global.u32 %0, [%1], %2;"
                 : "=r"(old) : "l"(&g_arrive), "r"(1u) : "memory");
    if (old + 1 == target){
      asm volatile("st.release.gpu.global.u32 [%0], %1;" :: "l"(&g_epoch), "r"(target) : "memory");
    } else {
      unsigned e; int spins = 0;
      do {
        asm volatile("ld.acquire.gpu.global.u32 %0, [%1];" : "=r"(e) : "l"(&g_epoch) : "memory");
        if (++spins > 32) __nanosleep(64);
      } while ((int)(e - target) < 0);
    }
  }
  __syncthreads();
}

__device__ __forceinline__ float act_fn(int act, float v){
  switch (act){
    case 0:  return 1.f/(1.f + __expf(-v));
    case 1:  return fmaxf(v, 0.f);
    case 2:  return v;
    default: return tanhf(v);
  }
}

// ---------------- split-K GEMM tile (2-term: Ah*Wh + Al*Wh) ----------------
// M=128, NLOC=64 local cols: n<32 -> gcol=j+n (c); n>=32 -> gcol=1024+j+(n-32) (h).
// 16 warps as 8(M)x2(N): warp tile 16m x 32n (16 c + 16 h, c/h pair in same thread).
// K-slice KC=256 in KB=32 chunks, double-buffered. fp32 partials to g_part.
__device__ __forceinline__ void gemm_tile(
    const bf16* __restrict__ ah, const bf16* __restrict__ al, long astr,
    const bf16* __restrict__ wh, int Kw,
    float* __restrict__ part, int j, bf16* smem, int tid)
{
  bf16* Asm = smem;
  bf16* Bsm = smem + SA_ELEMS;
  const int lane = tid & 31, warp = tid >> 5;
  const int wm = warp >> 1, wn = warp & 1;

  float C[4][4];
  #pragma unroll
  for (int n=0;n<4;n++)
    #pragma unroll
    for (int q=0;q<4;q++) C[n][q]=0.f;

  auto As_at = [&](int ver,int buf,int r,int c)->bf16*{
    return Asm + (((ver*2+buf)*128 + r)*APAD + c);
  };
  auto Bs_at = [&](int buf,int n,int c)->bf16*{
    return Bsm + ((buf*64 + n)*BPAD + c);
  };

  auto load_tiles = [&](int buf, int cc){
    const int koff = cc*KB;
    #pragma unroll
    for (int i=0;i<2;i++){               // A: 2ver x 128rows x 4 chunks = 1024
      int id  = tid + NT*i;
      int ver = id >> 9;
      int rid = id & 511;
      int row = rid >> 2, ch = rid & 3;
      cp16(As_at(ver, buf, row, ch*8), (ver?al:ah) + (size_t)row*astr + koff + ch*8);
    }
    if (tid < 256){                      // B: 64 n x 4 chunks = 256
      int n = tid >> 2, ch = tid & 3;
      int gcol = (n < 32) ? (j + n) : (NH + j + (n - 32));
      cp16(Bs_at(buf, n, ch*8), wh + (size_t)gcol*Kw + koff + ch*8);
    }
    cp_commit();
  };

  load_tiles(0, 0);
  #pragma unroll
  for (int cc = 0; cc < KC/KB; cc++){
    const int buf = cc & 1;
    if (cc + 1 < KC/KB){
      load_tiles(buf ^ 1, cc+1);
      asm volatile("cp.async.wait_group 1;\n");
    } else {
      asm volatile("cp.async.wait_group 0;\n");
    }
    __syncthreads();

    #pragma unroll
    for (int k16 = 0; k16 < KB; k16 += 16){
      uint32_t Ah[4], Al[4];
      {
        int r = wm*16 + (lane>>2);
        int c = k16 + 2*(lane&3);
        Ah[0] = *(uint32_t*)As_at(0,buf,r  ,c  );
        Ah[1] = *(uint32_t*)As_at(0,buf,r+8,c  );
        Ah[2] = *(uint32_t*)As_at(0,buf,r  ,c+8);
        Ah[3] = *(uint32_t*)As_at(0,buf,r+8,c+8);
        Al[0] = *(uint32_t*)As_at(1,buf,r  ,c  );
        Al[1] = *(uint32_t*)As_at(1,buf,r+8,c  );
        Al[2] = *(uint32_t*)As_at(1,buf,r  ,c+8);
        Al[3] = *(uint32_t*)As_at(1,buf,r+8,c+8);
      }
      uint32_t Bf[4][2];
      #pragma unroll
      for (int nt=0; nt<4; nt++){
        int n = ((nt<2) ? (wn*16 + nt*8) : (32 + wn*16 + (nt-2)*8)) + (lane>>2);
        int k = k16 + 2*(lane&3);
        Bf[nt][0] = *(uint32_t*)Bs_at(buf,n,k);
        Bf[nt][1] = *(uint32_t*)Bs_at(buf,n,k+8);
      }
      #pragma unroll
      for (int nt=0; nt<4; nt++){
        mma16816(C[nt], Ah, Bf[nt]);
        mma16816(C[nt], Al, Bf[nt]);
      }
    }
    __syncthreads();
  }

  // fp32 partials: C[nt] (c cols) with C[nt+2] (h cols)
  #pragma unroll
  for (int nt=0; nt<2; nt++){
    int r0 = wm*16 + (lane>>2);
    int gc = j + wn*16 + nt*8 + 2*(lane&3);
    *(float2*)(part + (size_t)r0*2048 + gc)            = make_float2(C[nt][0],   C[nt][1]);
    *(float2*)(part + (size_t)(r0+8)*2048 + gc)        = make_float2(C[nt][2],   C[nt][3]);
    *(float2*)(part + (size_t)r0*2048 + gc + 1024)     = make_float2(C[nt+2][0], C[nt+2][1]);
    *(float2*)(part + (size_t)(r0+8)*2048 + gc + 1024) = make_float2(C[nt+2][2], C[nt+2][3]);
  }
}

__device__ __forceinline__ float* part_ptr(int slice, int slot){
  return g_part[slice*3 + slot];
}

// ---------------- persistent scan kernel ----------------
__global__ void __launch_bounds__(NT,1) rnn_persistent(float* __restrict__ out){
  extern __shared__ __align__(16) bf16 smem[];
  const int tid = threadIdx.x;
  unsigned target = 0;

  for (int t = 0; t < TT; t++){
    // ---- G0: ch = [x_t | h] @ W0, 8 slices x 32 ntiles ----
    for (int it = blockIdx.x; it < 256; it += gridDim.x){
      int ntile = it >> 3, slice = it & 7;
      int kc0 = slice*KC;
      const bf16 *ah, *al; long astr;
      if (kc0 < 1024){ ah = g_xh + (size_t)t*NI + kc0; al = g_xl + (size_t)t*NI + kc0; astr = (long)TT*NI; }
      else           { ah = g_hh + (kc0-1024);         al = g_hl + (kc0-1024);         astr = NH; }
      gemm_tile(ah, al, astr, g_W0th + kc0, 2048, part_ptr(slice,0), ntile*32, smem, tid);
    }
    gsync(target);
    // ---- E0: s0 = h + sig(c)*(tanh(hh) - h), 8 slices ----
    for (int id = blockIdx.x*NT + tid; id < BB*NH; id += gridDim.x*NT){
      int row = id >> 10, col = id & 1023;
      float c = 0.f, hv = 0.f;
      #pragma unroll
      for (int s=0;s<8;s++){
        const float* p = part_ptr(s,0) + (size_t)row*2048;
        c  += __ldcg(p + col);
        hv += __ldcg(p + 1024 + col);
      }
      float sp = __ldcg(g_hbuf + id);
      float v = fmaf(1.f/(1.f+__expf(-c)), tanhf(hv) - sp, sp);
      g_s[0][id] = v;
      bf16 vh = __float2bfloat16(v);
      g_sh[0][id] = vh;
      g_sl[0][id] = __float2bfloat16(v - __bfloat162float(vh));
    }
    gsync(target);

    // ---- G1: gene0 (s0 @ W[0]), 4 slices x 32 ----
    for (int it = blockIdx.x; it < 128; it += gridDim.x){
      int ntile = it >> 2, slice = it & 3;
      int kc0 = slice*KC;
      gemm_tile(g_sh[0] + kc0, g_sl[0] + kc0, NH,
                g_Wsth[0] + kc0, 1024, part_ptr(slice,0), ntile*32, smem, tid);
    }
    gsync(target);
    // ---- E1: s1 (sigmoid, resid s0), 4 slices ----
    for (int id = blockIdx.x*NT + tid; id < BB*NH; id += gridDim.x*NT){
      int row = id >> 10, col = id & 1023;
      float c = 0.f, hv = 0.f;
      #pragma unroll
      for (int s=0;s<4;s++){
        const float* p = part_ptr(s,0) + (size_t)row*2048;
        c  += __ldcg(p + col);
        hv += __ldcg(p + 1024 + col);
      }
      float sp = __ldcg(&g_s[0][id]);
      float v = fmaf(1.f/(1.f+__expf(-c)), act_fn(0,hv) - sp, sp);
      g_s[1][id] = v;
      bf16 vh = __float2bfloat16(v);
      g_sh[1][id] = vh;
      g_sl[1][id] = __float2bfloat16(v - __bfloat162float(vh));
    }
    gsync(target);

    // ---- G2: genes 1,2,3 from s1; 3 slots x 32 ntiles x 4 slices ----
    for (int it = blockIdx.x; it < 384; it += gridDim.x){
      int slot = it >> 7, rem = it & 127;
      int ntile = rem >> 2, slice = rem & 3;
      int gi = 1 + slot;
      int kc0 = slice*KC;
      gemm_tile(g_sh[1] + kc0, g_sl[1] + kc0, NH,
                g_Wsth[gi] + kc0, 1024, part_ptr(slice,slot), ntile*32, smem, tid);
    }
    gsync(target);
    // ---- E2: s2 (relu), s3 (relu), s4 (identity); resid s1 ----
    for (int id = blockIdx.x*NT + tid; id < 3*BB*NH; id += gridDim.x*NT){
      int slot = id >> 17, rid = id & (BB*NH-1);
      int row = rid >> 10, col = rid & 1023;
      float c = 0.f, hv = 0.f;
      #pragma unroll
      for (int s=0;s<4;s++){
        const float* p = part_ptr(s,slot) + (size_t)row*2048;
        c  += __ldcg(p + col);
        hv += __ldcg(p + 1024 + col);
      }
      int act = (slot==2) ? 2 : 1;
      float sp = __ldcg(&g_s[1][rid]);
      float v = fmaf(1.f/(1.f+__expf(-c)), act_fn(act,hv) - sp, sp);
      int dst = slot + 2;
      g_s[dst][rid] = v;
      if (dst < 4){
        bf16 vh = __float2bfloat16(v);
        g_sh[dst][rid] = vh;
        g_sl[dst][rid] = __float2bfloat16(v - __bfloat162float(vh));
      }
    }
    gsync(target);

    // ---- G3: gene4 (s2) slot0, gene6 (s3) slot1 ----
    for (int it = blockIdx.x; it < 256; it += gridDim.x){
      int slot = it >> 7, rem = it & 127;
      int ntile = rem >> 2, slice = rem & 3;
      int gi = 4 + slot*2;
      int src = 2 + slot;
      int kc0 = slice*KC;
      gemm_tile(g_sh[src] + kc0, g_sl[src] + kc0, NH,
                g_Wsth[gi] + kc0, 1024, part_ptr(slice,slot), ntile*32, smem, tid);
    }
    gsync(target);
    // ---- E3: s5 (tanh, resid s2), s7 (tanh, resid s3) ----
    for (int id = blockIdx.x*NT + tid; id < 2*BB*NH; id += gridDim.x*NT){
      int slot = id >> 17, rid = id & (BB*NH-1);
      int row = rid >> 10, col = rid & 1023;
      float c = 0.f, hv = 0.f;
      #pragma unroll
      for (int s=0;s<4;s++){
        const float* p = part_ptr(s,slot) + (size_t)row*2048;
        c  += __ldcg(p + col);
        hv += __ldcg(p + 1024 + col);
      }
      float sp = __ldcg(&g_s[2+slot][rid]);
      float v = fmaf(1.f/(1.f+__expf(-c)), tanhf(hv) - sp, sp);
      int dst = (slot==0) ? 5 : 7;
      g_s[dst][rid] = v;
      if (dst == 5){
        bf16 vh = __float2bfloat16(v);
        g_sh[5][rid] = vh;
        g_sl[5][rid] = __float2bfloat16(v - __bfloat162float(vh));
      }
    }
    gsync(target);

    // ---- G4: gene5 slot0, gene7 slot1, both from s5 ----
    for (int it = blockIdx.x; it < 256; it += gridDim.x){
      int slot = it >> 7, rem = it & 127;
      int ntile = rem >> 2, slice = rem & 3;
      int gi = 5 + slot*2;
      int kc0 = slice*KC;
      gemm_tile(g_sh[5] + kc0, g_sl[5] + kc0, NH,
                g_Wsth[gi] + kc0, 1024, part_ptr(slice,slot), ntile*32, smem, tid);
    }
    gsync(target);
    // ---- E4 + finalize: s6 (sig), s8 (relu), resid s5; h = mean(s1..s8) ----
    for (int id = blockIdx.x*NT + tid; id < BB*NH; id += gridDim.x*NT){
      int row = id >> 10, col = id & 1023;
      float c6=0.f, h6=0.f, c8=0.f, h8=0.f;
      #pragma unroll
      for (int s=0;s<4;s++){
        const float* p0 = part_ptr(s,0) + (size_t)row*2048;
        const float* p1 = part_ptr(s,1) + (size_t)row*2048;
        c6 += __ldcg(p0 + col);  h6 += __ldcg(p0 + 1024 + col);
        c8 += __ldcg(p1 + col);  h8 += __ldcg(p1 + 1024 + col);
      }
      float s5 = __ldcg(&g_s[5][id]);
      float s6 = fmaf(1.f/(1.f+__expf(-c6)), (1.f/(1.f+__expf(-h6))) - s5, s5);
      float s8 = fmaf(1.f/(1.f+__expf(-c8)), fmaxf(h8,0.f) - s5, s5);
      float m = __ldcg(&g_s[1][id]) + __ldcg(&g_s[2][id]) + __ldcg(&g_s[3][id])
              + __ldcg(&g_s[4][id]) + s5 + s6 + __ldcg(&g_s[7][id]) + s8;
      m *= 0.125f;
      g_hbuf[id] = m;
      bf16 mh = __float2bfloat16(m);
      g_hh[id] = mh;
      g_hl[id] = __float2bfloat16(m - __bfloat162float(mh));
      out[((size_t)row*TT + t)*NH + col] = m;
      if (t == TT-1) out[(size_t)BB*TT*NH + id] = m;
    }
    gsync(target);
  }
}

// ---------------- prologue helpers ----------------
__global__ void split_kernel(const float* __restrict__ src, bf16* __restrict__ hi,
                             bf16* __restrict__ lo, float* __restrict__ fcopy, int n){
  int i = blockIdx.x*blockDim.x + threadIdx.x;
  int stride = gridDim.x*blockDim.x;
  for (; i < n; i += stride){
    float v = src[i];
    bf16 h = __float2bfloat16(v);
    hi[i] = h;
    lo[i] = __float2bfloat16(v - __bfloat162float(h));
    if (fcopy) fcopy[i] = v;
  }
}

// transpose + bf16(hi): in [K][N] fp32 -> out [N][K] bf16. One z-slice per gene.
__global__ void tsplit_kernel(const float* __restrict__ in, bf16* __restrict__ outh,
                              int K, int N){
  __shared__ float tile[32][33];
  const float* src = in + (size_t)blockIdx.z*K*N;
  bf16* oh = outh + (size_t)blockIdx.z*N*K;
  int tx = threadIdx.x, ty = threadIdx.y;
  int n0 = blockIdx.x*32, k0 = blockIdx.y*32;
  #pragma unroll
  for (int r=0;r<4;r++)
    tile[ty + r*8][tx] = src[(size_t)(k0 + ty + r*8)*N + n0 + tx];
  __syncthreads();
  #pragma unroll
  for (int r=0;r<4;r++){
    float v = tile[tx][ty + r*8];
    oh[(size_t)(n0 + ty + r*8)*K + k0 + tx] = __float2bfloat16(v);
  }
}

__global__ void reset_kernel(){ g_arrive = 0; g_epoch = 0; }

// ---------------- host launch ----------------
extern "C" void kernel_launch(void* const* d_in, const int* in_sizes, int n_in,
                              void* d_out, int out_size){
  const float *x=nullptr, *h0=nullptr, *W0=nullptr, *Ws=nullptr;
  for (int i=0;i<n_in;i++){
    long n = in_sizes[i];
    if      (n == (long)BB*TT*NI)   x  = (const float*)d_in[i];
    else if (n == (long)BB*NH)      h0 = (const float*)d_in[i];
    else if (n == (long)2048*2048)  W0 = (const float*)d_in[i];
    else if (n == (long)8*NH*2048)  Ws = (const float*)d_in[i];
  }
  if (!x || !h0 || !W0 || !Ws) return;
  float* out = (float*)d_out;

  void* p;
  cudaGetSymbolAddress(&p, g_hbuf); float* h_p  = (float*)p;
  cudaGetSymbolAddress(&p, g_hh);   bf16*  hh_p = (bf16*)p;
  cudaGetSymbolAddress(&p, g_hl);   bf16*  hl_p = (bf16*)p;
  cudaGetSymbolAddress(&p, g_xh);   bf16*  xh_p = (bf16*)p;
  cudaGetSymbolAddress(&p, g_xl);   bf16*  xl_p = (bf16*)p;
  cudaGetSymbolAddress(&p, g_W0th); bf16*  w0h_p= (bf16*)p;
  cudaGetSymbolAddress(&p, g_Wsth); bf16*  wsh_p= (bf16*)p;

  cudaFuncSetAttribute(rnn_persistent, cudaFuncAttributeMaxDynamicSharedMemorySize, SMEM_BYTES);

  int dev = 0, nsm = 0, maxblk = 0;
  cudaGetDevice(&dev);
  cudaDeviceGetAttribute(&nsm, cudaDevAttrMultiProcessorCount, dev);
  cudaOccupancyMaxActiveBlocksPerMultiprocessor(&maxblk, rnn_persistent, NT, SMEM_BYTES);
  if (maxblk < 1) maxblk = 1;
  int grid = nsm * maxblk;

  // prologue: transpose weights (hi only), split inputs and initial hidden
  tsplit_kernel<<<dim3(64,64,1), dim3(32,8)>>>(W0, w0h_p, 2048, 2048);
  tsplit_kernel<<<dim3(64,32,8), dim3(32,8)>>>(Ws, wsh_p, 1024, 2048);
  split_kernel<<<8192,256>>>(x, xh_p, xl_p, nullptr, BB*TT*NI);
  split_kernel<<<512,256>>>(h0, hh_p, hl_p, h_p, BB*NH);
  reset_kernel<<<1,1>>>();

  rnn_persistent<<<grid, NT, SMEM_BYTES>>>(out);
  (void)out_size;
}